// round 1
// baseline (speedup 1.0000x reference)
#include <cuda_runtime.h>
#include <math.h>

// Problem constants
#define HH 56
#define WW 56
#define NB 16
#define CIN0 64
#define COUT0 128
#define MU_C 0.1f
#define THR_C 0.01f   // MU * LAMBDA

// Scratch (allocation-free: device globals)
__device__ float g_Wn [COUT0 * CIN0 * 9];   // normalized weights [128][64][9]
__device__ float g_WnT[CIN0 * COUT0 * 9];   // flipped/transposed  [64][128][9]
__device__ float g_y    [NB * COUT0 * HH * WW];
__device__ float g_cprev[NB * COUT0 * HH * WW];
__device__ float g_r    [NB * CIN0 * HH * WW];

// ---------------------------------------------------------------------------
// Weight normalization: Wn[o] = W[o] / sqrt(sum(W[o]^2)+1e-12)
// Also builds WnT[ci][co][k'] = Wn[co][ci][8-k] for the transpose conv.
// ---------------------------------------------------------------------------
__global__ void normalize_kernel(const float* __restrict__ W) {
    const int co = blockIdx.x;          // 0..127
    const int tid = threadIdx.x;        // 0..255
    __shared__ float red[256];
    float s = 0.f;
    for (int i = tid; i < 576; i += 256) {
        float v = W[co * 576 + i];
        s += v * v;
    }
    red[tid] = s;
    __syncthreads();
    for (int off = 128; off > 0; off >>= 1) {
        if (tid < off) red[tid] += red[tid + off];
        __syncthreads();
    }
    const float inv = 1.0f / sqrtf(red[0] + 1e-12f);
    for (int i = tid; i < 576; i += 256) {
        float v = W[co * 576 + i] * inv;
        g_Wn[co * 576 + i] = v;
        int ci = i / 9, k = i - ci * 9;
        g_WnT[ci * (COUT0 * 9) + co * 9 + (8 - k)] = v;
    }
}

// ---------------------------------------------------------------------------
// Fused 3x3 conv (stride 1, pad 1) + epilogues.
// MODE 0: first forward:  v = relu(MU*acc - THR); out0[=y] = v; out1[=cprev] = v
// MODE 1: FISTA forward:  cn = relu(aux0[y] + MU*acc - THR);
//                         out1[=cprev or d_out] = cn;
//                         if write_y: out0[=y] = cn + m*(cn - aux1[cprev])
// MODE 2: transpose conv residual: out0[=r] = aux0[x] - acc
//
// Tiling: block (28,8)=224 threads, tile 8 rows x 56 cols, 2 px/thread,
// CO_T=16 output channels per block, CI_T=8 input channels staged in smem.
// ---------------------------------------------------------------------------
template <int CIN, int COUT, int MODE>
__global__ __launch_bounds__(224)
void conv3x3_kernel(const float* __restrict__ in,
                    const float* __restrict__ wgt,
                    const float* __restrict__ aux0,
                    const float* __restrict__ aux1,
                    float* __restrict__ out0,
                    float* __restrict__ out1,
                    float m, int write_y)
{
    const int n   = blockIdx.z;
    const int h0  = blockIdx.y * 8;
    const int co0 = blockIdx.x * 16;
    const int tx  = threadIdx.x;            // 0..27
    const int ty  = threadIdx.y;            // 0..7
    const int tid = ty * 28 + tx;

    __shared__ float s_in[8 * 10 * 58];     // [ci][row 0..9][col 0..57]
    __shared__ float s_w [16 * 8 * 9];      // [co][ci][k]

    float acc[16][2];
#pragma unroll
    for (int i = 0; i < 16; i++) { acc[i][0] = 0.f; acc[i][1] = 0.f; }

    for (int cb = 0; cb < CIN; cb += 8) {
        __syncthreads();
        // stage input halo tile (10 rows x 58 cols x 8 ci), zero-padded
        for (int idx = tid; idx < 8 * 10 * 58; idx += 224) {
            int ci  = idx / 580;
            int rem = idx - ci * 580;
            int r   = rem / 58;
            int c   = rem - r * 58;
            int gh  = h0 + r - 1;
            int gw  = c - 1;
            float v = 0.f;
            if ((unsigned)gh < (unsigned)HH && (unsigned)gw < (unsigned)WW)
                v = in[((n * CIN + cb + ci) * HH + gh) * WW + gw];
            s_in[idx] = v;
        }
        // stage weights: [co 0..15][ci 0..7][k 0..8]
        for (int idx = tid; idx < 16 * 8 * 9; idx += 224) {
            int co  = idx / 72;
            int rem = idx - co * 72;                // rem = ci*9 + k
            s_w[idx] = wgt[(co0 + co) * (CIN * 9) + cb * 9 + rem];
        }
        __syncthreads();

        for (int ci = 0; ci < 8; ci++) {
            float a[3][4];
#pragma unroll
            for (int r = 0; r < 3; r++)
#pragma unroll
                for (int c = 0; c < 4; c++)
                    a[r][c] = s_in[ci * 580 + (ty + r) * 58 + 2 * tx + c];
#pragma unroll
            for (int co = 0; co < 16; co++) {
                const float* wp = &s_w[co * 72 + ci * 9];
#pragma unroll
                for (int r = 0; r < 3; r++)
#pragma unroll
                    for (int c = 0; c < 3; c++) {
                        float wv = wp[r * 3 + c];
                        acc[co][0] = fmaf(wv, a[r][c],     acc[co][0]);
                        acc[co][1] = fmaf(wv, a[r][c + 1], acc[co][1]);
                    }
            }
        }
    }

    // epilogue
    const int h = h0 + ty;
    const int wb = 2 * tx;
#pragma unroll
    for (int co = 0; co < 16; co++) {
        int o = ((n * COUT + co0 + co) * HH + h) * WW + wb;
#pragma unroll
        for (int p = 0; p < 2; p++) {
            float v = acc[co][p];
            if (MODE == 0) {
                float cval = fmaxf(MU_C * v - THR_C, 0.f);
                out0[o + p] = cval;
                out1[o + p] = cval;
            } else if (MODE == 1) {
                float yv = aux0[o + p];
                float cp = aux1[o + p];
                float cn = fmaxf(yv + MU_C * v - THR_C, 0.f);
                out1[o + p] = cn;
                if (write_y) out0[o + p] = cn + m * (cn - cp);
            } else {
                out0[o + p] = aux0[o + p] - v;
            }
        }
    }
}

// ---------------------------------------------------------------------------
extern "C" void kernel_launch(void* const* d_in, const int* in_sizes, int n_in,
                              void* d_out, int out_size)
{
    const float* x = (const float*)d_in[0];   // [16,64,56,56]
    const float* W = (const float*)d_in[1];   // [128,64,3,3]
    float* out = (float*)d_out;               // [16,128,56,56]

    float *Wn, *WnT, *y, *cprev, *r;
    cudaGetSymbolAddress((void**)&Wn,    g_Wn);
    cudaGetSymbolAddress((void**)&WnT,   g_WnT);
    cudaGetSymbolAddress((void**)&y,     g_y);
    cudaGetSymbolAddress((void**)&cprev, g_cprev);
    cudaGetSymbolAddress((void**)&r,     g_r);

    // FISTA momentum coefficients, computed in double on host
    float mv[5];
    {
        double t = 1.0;
        for (int i = 0; i < 5; i++) {
            double tn = (1.0 + sqrt(1.0 + 4.0 * t * t)) / 2.0;
            mv[i] = (float)((t - 1.0) / tn);
            t = tn;
        }
    }

    dim3 blk(28, 8, 1);
    dim3 grid_f(COUT0 / 16, HH / 8, NB);   // (8,7,16)
    dim3 grid_t(CIN0 / 16,  HH / 8, NB);   // (4,7,16)

    normalize_kernel<<<128, 256>>>(W);

    // iteration 0: c = shrink(MU * D^T x); y = c; c_prev = c
    conv3x3_kernel<CIN0, COUT0, 0><<<grid_f, blk>>>(
        x, Wn, nullptr, nullptr, y, cprev, 0.f, 0);

    for (int it = 0; it < 5; it++) {
        // r = x - D y   (transpose conv fused with residual)
        conv3x3_kernel<COUT0, CIN0, 2><<<grid_t, blk>>>(
            y, WnT, x, nullptr, r, nullptr, 0.f, 0);
        // c_new = shrink(y + MU * D^T r); momentum update
        const int last = (it == 4);
        conv3x3_kernel<CIN0, COUT0, 1><<<grid_f, blk>>>(
            r, Wn, y, cprev, y, last ? out : cprev, mv[it], last ? 0 : 1);
    }
}

// round 4
// speedup vs baseline: 4.5640x; 4.5640x over previous
#include <cuda_runtime.h>
#include <cstdint>
#include <math.h>

#define HH 56
#define WW 56
#define NB 16
#define C1 64
#define C2 128
#define MU_C 0.1f
#define THR_C 0.01f

// ---------------- device scratch (allocation-free) ----------------
// fragment-ordered weights: [cib][tap][co_blk][kblk(4)][lane(32)][2]
__device__ float g_Wf[2 * 9 * (C2 / 8) * 4 * 64];   // 73728 floats
__device__ float g_Wt[4 * 9 * (C1 / 8) * 4 * 64];   // 73728 floats
__device__ float g_xn[NB * HH * WW * C1];           // x in NHWC
__device__ float g_y [NB * HH * WW * C2];
__device__ float g_cp[NB * HH * WW * C2];
__device__ float g_r [NB * HH * WW * C1];

__device__ __forceinline__ float rna_tf32(float v) {
    uint32_t o;
    asm("cvt.rna.tf32.f32 %0, %1;" : "=r"(o) : "f"(v));
    return __uint_as_float(o);
}

__device__ __forceinline__ void mma_tf32(float* d, const uint32_t* a, const uint32_t* b) {
    asm volatile(
        "mma.sync.aligned.m16n8k8.row.col.f32.tf32.tf32.f32 "
        "{%0,%1,%2,%3}, {%4,%5,%6,%7}, {%8,%9}, {%0,%1,%2,%3};"
        : "+f"(d[0]), "+f"(d[1]), "+f"(d[2]), "+f"(d[3])
        : "r"(a[0]), "r"(a[1]), "r"(a[2]), "r"(a[3]), "r"(b[0]), "r"(b[1]));
}

#define SWZ(o) ((o) ^ (((o) >> 3) & 0x70))

// ---------------- prep kernels ----------------
__global__ void nchw2nhwc_kernel(const float* __restrict__ src, float* __restrict__ dst) {
    int i = blockIdx.x * 256 + threadIdx.x;
    int total = NB * HH * WW * C1;
    if (i >= total) return;
    int c = i & 63;
    int p = i >> 6;
    int w = p % WW;
    int q = p / WW;
    int h = q % HH;
    int n = q / HH;
    dst[i] = src[((n * C1 + c) * HH + h) * WW + w];
}

// normalize + scatter into mma-fragment order for fwd and transpose conv
__global__ void prep_w_kernel(const float* __restrict__ W) {
    const int co = blockIdx.x;      // 0..127
    const int tid = threadIdx.x;    // 0..255
    __shared__ float red[256];
    float s = 0.f;
    for (int i = tid; i < 576; i += 256) {
        float v = W[co * 576 + i];
        s += v * v;
    }
    red[tid] = s;
    __syncthreads();
    for (int off = 128; off > 0; off >>= 1) {
        if (tid < off) red[tid] += red[tid + off];
        __syncthreads();
    }
    const float inv = rsqrtf(red[0] + 1e-12f);
    for (int i = tid; i < 576; i += 256) {
        int ci = i / 9, tap = i - ci * 9;
        float v = rna_tf32(W[co * 576 + i] * inv);
        // forward: n = co, k = ci
        {
            int lane = (co & 7) * 4 + (ci & 3);
            int reg  = (ci >> 2) & 1;
            int idx = (((((ci >> 5) * 9 + tap) * (C2 / 8) + (co >> 3)) * 4 +
                        ((ci & 31) >> 3)) * 32 + lane) * 2 + reg;
            g_Wf[idx] = v;
        }
        // transpose: n = ci (out ch), k = co, flipped tap
        {
            int lane = (ci & 7) * 4 + (co & 3);
            int reg  = (co >> 2) & 1;
            int idx = (((((co >> 5) * 9 + (8 - tap)) * (C1 / 8) + (ci >> 3)) * 4 +
                        ((co & 31) >> 3)) * 32 + lane) * 2 + reg;
            g_Wt[idx] = v;
        }
    }
}

// ---------------- mma.sync implicit-GEMM conv ----------------
// D[m=128 px (2 rows x 64 cols)][n=64 cout], K = 9 taps x CIN ci.
// MODE 0: first fwd;  MODE 1: FISTA fwd;  MODE 2: transpose conv + residual
template <int CIN, int COUT, int MODE>
__global__ __launch_bounds__(256)
void mconv(const float* __restrict__ in, const float* __restrict__ wgt,
           const float* __restrict__ aux0, const float* __restrict__ aux1,
           float* __restrict__ out0, float* __restrict__ out1,
           float mcoef, int last)
{
    extern __shared__ char smem[];
    float* sA = (float*)smem;              // 256 rows x 32 ci, SW128 rows (32 KB)
    float* sB = (float*)(smem + 32768);    // [tap][nbl 8][kblk 4][lane][2]  (72 KB)

    const int tid  = threadIdx.x;
    const int lane = tid & 31;
    const int w    = tid >> 5;
    const int wm   = w & 3;                // m32 chunk of 4
    const int wn   = w >> 2;               // n32 chunk of 2
    const int g    = lane >> 2;
    const int t    = lane & 3;

    const int n   = blockIdx.z;
    const int h0  = blockIdx.y * 2;
    const int co0 = blockIdx.x * 64;
    const int cb0 = co0 >> 3;              // global co_blk base
    constexpr int KH  = CIN / 32;
    constexpr int NBG = COUT / 8;

    float acc[2][4][4];
#pragma unroll
    for (int c = 0; c < 2; c++)
#pragma unroll
        for (int nb = 0; nb < 4; nb++)
#pragma unroll
            for (int j = 0; j < 4; j++) acc[c][nb][j] = 0.f;

    for (int kh = 0; kh < KH; kh++) {
        if (kh) __syncthreads();
        // ---- stage A: 4 halo rows x 64 cols x 32 ci (tf32-rounded)
        for (int i4 = tid; i4 < 2048; i4 += 256) {
            int row = i4 >> 3;             // m' = rr*64 + cc
            int c4  = i4 & 7;
            int rr = row >> 6, cc = row & 63;
            int gh = h0 + rr - 1, gc = cc - 1;
            float4 v = make_float4(0.f, 0.f, 0.f, 0.f);
            if ((unsigned)gh < (unsigned)HH && (unsigned)gc < (unsigned)WW) {
                float4 s = *(const float4*)(in +
                    (size_t)((n * HH + gh) * WW + gc) * CIN + kh * 32 + c4 * 4);
                v.x = rna_tf32(s.x); v.y = rna_tf32(s.y);
                v.z = rna_tf32(s.z); v.w = rna_tf32(s.w);
            }
            *(float4*)((char*)sA + SWZ(row * 128 + c4 * 16)) = v;
        }
        // ---- stage B: fragment-ordered weight slice for this stage / co window
        for (int i4 = tid; i4 < 4608; i4 += 256) {
            int tap = i4 >> 9;
            int rem = i4 & 511;
            int nbl = rem >> 6;
            int q4  = rem & 63;
            float4 v = *(const float4*)(wgt +
                (size_t)(((kh * 9 + tap) * NBG + cb0 + nbl) * 256 + q4 * 4));
            *(float4*)(sB + (tap * 8 + nbl) * 256 + q4 * 4) = v;
        }
        __syncthreads();

        // ---- compute: 9 taps x 4 k8 blocks
#pragma unroll
        for (int tap = 0; tap < 9; tap++) {
            const int tapoff = (tap / 3) * 64 + (tap % 3);
#pragma unroll
            for (int kblk = 0; kblk < 4; kblk++) {
                const int k0 = kblk * 8;
                uint32_t a[2][4];
#pragma unroll
                for (int c = 0; c < 2; c++) {
                    int mb = wm * 32 + c * 16 + g + tapoff;   // fragment row m'
                    int x0 = (mb & 7) << 4;
                    int x1 = ((mb + 8) & 7) << 4;
                    const char* pA = (const char*)sA;
                    a[c][0] = *(const uint32_t*)(pA + mb * 128 +       (((k0 + t) * 4)     ^ x0));
                    a[c][1] = *(const uint32_t*)(pA + (mb + 8) * 128 + (((k0 + t) * 4)     ^ x1));
                    a[c][2] = *(const uint32_t*)(pA + mb * 128 +       (((k0 + t + 4) * 4) ^ x0));
                    a[c][3] = *(const uint32_t*)(pA + (mb + 8) * 128 + (((k0 + t + 4) * 4) ^ x1));
                }
#pragma unroll
                for (int nb = 0; nb < 4; nb++) {
                    const float* bp = sB + ((tap * 8 + wn * 4 + nb) * 4 + kblk) * 64 + lane * 2;
                    uint32_t b[2];
                    b[0] = __float_as_uint(bp[0]);
                    b[1] = __float_as_uint(bp[1]);
                    mma_tf32(acc[0][nb], a[0], b);
                    mma_tf32(acc[1][nb], a[1], b);
                }
            }
        }
    }

    // ---- epilogue: fused FISTA ops on register fragments
#pragma unroll
    for (int c = 0; c < 2; c++) {
#pragma unroll
        for (int half = 0; half < 2; half++) {
            int m = wm * 32 + c * 16 + g + half * 8;   // pixel index in tile
            int rr = m >> 6, cc = m & 63;
            if (cc >= WW) continue;
            int h = h0 + rr;
            size_t pxb = (size_t)((n * HH + h) * WW + cc) * COUT + co0;
#pragma unroll
            for (int nb = 0; nb < 4; nb++) {
                int col = wn * 32 + nb * 8 + 2 * t;
                size_t o = pxb + col;
                float v0 = acc[c][nb][half * 2 + 0];
                float v1 = acc[c][nb][half * 2 + 1];
                if (MODE == 0) {
                    float2 r2;
                    r2.x = fmaxf(MU_C * v0 - THR_C, 0.f);
                    r2.y = fmaxf(MU_C * v1 - THR_C, 0.f);
                    *(float2*)(out0 + o) = r2;
                    *(float2*)(out1 + o) = r2;
                } else if (MODE == 1) {
                    float2 yv = *(const float2*)(aux0 + o);
                    float cn0 = fmaxf(yv.x + MU_C * v0 - THR_C, 0.f);
                    float cn1 = fmaxf(yv.y + MU_C * v1 - THR_C, 0.f);
                    if (last) {
                        out1[((size_t)(n * C2 + co0 + col) * HH + h) * WW + cc] = cn0;
                        out1[((size_t)(n * C2 + co0 + col + 1) * HH + h) * WW + cc] = cn1;
                    } else {
                        float2 cpv = *(const float2*)(aux1 + o);
                        float2 c2; c2.x = cn0; c2.y = cn1;
                        *(float2*)(out1 + o) = c2;
                        float2 y2;
                        y2.x = cn0 + mcoef * (cn0 - cpv.x);
                        y2.y = cn1 + mcoef * (cn1 - cpv.y);
                        *(float2*)(out0 + o) = y2;
                    }
                } else {
                    float2 xv = *(const float2*)(aux0 + o);
                    float2 r2;
                    r2.x = xv.x - v0;
                    r2.y = xv.y - v1;
                    *(float2*)(out0 + o) = r2;
                }
            }
        }
    }
}

// ---------------- launcher ----------------
extern "C" void kernel_launch(void* const* d_in, const int* in_sizes, int n_in,
                              void* d_out, int out_size)
{
    const float* x = (const float*)d_in[0];   // [16,64,56,56] NCHW
    const float* W = (const float*)d_in[1];   // [128,64,3,3]
    float* out = (float*)d_out;               // [16,128,56,56] NCHW

    float *Wf, *Wt, *xn, *y, *cp, *r;
    cudaGetSymbolAddress((void**)&Wf, g_Wf);
    cudaGetSymbolAddress((void**)&Wt, g_Wt);
    cudaGetSymbolAddress((void**)&xn, g_xn);
    cudaGetSymbolAddress((void**)&y,  g_y);
    cudaGetSymbolAddress((void**)&cp, g_cp);
    cudaGetSymbolAddress((void**)&r,  g_r);

    float mv[5];
    {
        double t = 1.0;
        for (int i = 0; i < 5; i++) {
            double tn = (1.0 + sqrt(1.0 + 4.0 * t * t)) / 2.0;
            mv[i] = (float)((t - 1.0) / tn);
            t = tn;
        }
    }

    const int SMEM = 32768 + 73728;   // 106496 B
    cudaFuncSetAttribute(mconv<C1, C2, 0>, cudaFuncAttributeMaxDynamicSharedMemorySize, SMEM);
    cudaFuncSetAttribute(mconv<C1, C2, 1>, cudaFuncAttributeMaxDynamicSharedMemorySize, SMEM);
    cudaFuncSetAttribute(mconv<C2, C1, 2>, cudaFuncAttributeMaxDynamicSharedMemorySize, SMEM);

    int total = NB * HH * WW * C1;
    nchw2nhwc_kernel<<<(total + 255) / 256, 256>>>(x, xn);
    prep_w_kernel<<<128, 256>>>(W);

    dim3 blk(256, 1, 1);
    dim3 grid_f(C2 / 64, HH / 2, NB);   // (2, 28, 16)
    dim3 grid_t(C1 / 64, HH / 2, NB);   // (1, 28, 16)

    // iteration 0: c = shrink(MU * D^T x); y = c; cp = c
    mconv<C1, C2, 0><<<grid_f, blk, SMEM>>>(xn, Wf, nullptr, nullptr, y, cp, 0.f, 0);

    for (int it = 0; it < 5; it++) {
        // r = x - D y  (transpose conv + residual)
        mconv<C2, C1, 2><<<grid_t, blk, SMEM>>>(y, Wt, xn, nullptr, r, nullptr, 0.f, 0);
        // c_new = shrink(y + MU * D^T r); momentum
        const int last = (it == 4);
        mconv<C1, C2, 1><<<grid_f, blk, SMEM>>>(r, Wf, y, cp, y, last ? out : cp,
                                                mv[it], last);
    }
}

// round 5
// speedup vs baseline: 4.6602x; 1.0211x over previous
#include <cuda_runtime.h>
#include <cstdint>
#include <math.h>

#define HH 56
#define WW 56
#define NB 16
#define C1 64
#define C2 128
#define MU_C 0.1f
#define THR_C 0.01f

// ---------------- device scratch (allocation-free) ----------------
// fragment-ordered weights: [cib][tap][co_blk][kblk(4)][lane(32)][2]
__device__ float g_Wf[2 * 9 * (C2 / 8) * 4 * 64];   // 73728 floats
__device__ float g_Wt[4 * 9 * (C1 / 8) * 4 * 64];   // 73728 floats
__device__ float g_xn[NB * HH * WW * C1];           // x in NHWC
__device__ float g_y [NB * HH * WW * C2];
__device__ float g_cp[NB * HH * WW * C2];
__device__ float g_r [NB * HH * WW * C1];

__device__ __forceinline__ float rna_tf32(float v) {
    uint32_t o;
    asm("cvt.rna.tf32.f32 %0, %1;" : "=r"(o) : "f"(v));
    return __uint_as_float(o);
}

__device__ __forceinline__ void mma_tf32(float* d, const uint32_t* a, const uint32_t* b) {
    asm volatile(
        "mma.sync.aligned.m16n8k8.row.col.f32.tf32.tf32.f32 "
        "{%0,%1,%2,%3}, {%4,%5,%6,%7}, {%8,%9}, {%0,%1,%2,%3};"
        : "+f"(d[0]), "+f"(d[1]), "+f"(d[2]), "+f"(d[3])
        : "r"(a[0]), "r"(a[1]), "r"(a[2]), "r"(a[3]), "r"(b[0]), "r"(b[1]));
}

#define SWZ(o) ((o) ^ (((o) >> 3) & 0x70))

// ---------------- prep kernels ----------------
__global__ void nchw2nhwc_kernel(const float* __restrict__ src, float* __restrict__ dst) {
    int i = blockIdx.x * 256 + threadIdx.x;
    int total = NB * HH * WW * C1;
    if (i >= total) return;
    int c = i & 63;
    int p = i >> 6;
    int w = p % WW;
    int q = p / WW;
    int h = q % HH;
    int n = q / HH;
    dst[i] = src[((n * C1 + c) * HH + h) * WW + w];
}

// normalize + scatter into mma-fragment order for fwd and transpose conv
__global__ void prep_w_kernel(const float* __restrict__ W) {
    const int co = blockIdx.x;      // 0..127
    const int tid = threadIdx.x;    // 0..255
    __shared__ float red[256];
    float s = 0.f;
    for (int i = tid; i < 576; i += 256) {
        float v = W[co * 576 + i];
        s += v * v;
    }
    red[tid] = s;
    __syncthreads();
    for (int off = 128; off > 0; off >>= 1) {
        if (tid < off) red[tid] += red[tid + off];
        __syncthreads();
    }
    const float inv = rsqrtf(red[0] + 1e-12f);
    for (int i = tid; i < 576; i += 256) {
        int ci = i / 9, tap = i - ci * 9;
        float v = rna_tf32(W[co * 576 + i] * inv);
        // forward: n = co, k = ci
        {
            int lane = (co & 7) * 4 + (ci & 3);
            int reg  = (ci >> 2) & 1;
            int idx = (((((ci >> 5) * 9 + tap) * (C2 / 8) + (co >> 3)) * 4 +
                        ((ci & 31) >> 3)) * 32 + lane) * 2 + reg;
            g_Wf[idx] = v;
        }
        // transpose: n = ci (out ch), k = co, flipped tap
        {
            int lane = (ci & 7) * 4 + (co & 3);
            int reg  = (co >> 2) & 1;
            int idx = (((((co >> 5) * 9 + (8 - tap)) * (C1 / 8) + (ci >> 3)) * 4 +
                        ((co & 31) >> 3)) * 32 + lane) * 2 + reg;
            g_Wt[idx] = v;
        }
    }
}

// ---------------- mma.sync implicit-GEMM conv ----------------
// D[m=128 px (2 rows x 64 cols)][n=64 cout], K = 9 taps x CIN ci.
// MODE 0: first fwd;  MODE 1: FISTA fwd;  MODE 2: transpose conv + residual
template <int CIN, int COUT, int MODE>
__global__ __launch_bounds__(256, 2)
void mconv(const float* __restrict__ in, const float* __restrict__ wgt,
           const float* __restrict__ aux0, const float* __restrict__ aux1,
           float* __restrict__ out0, float* __restrict__ out1,
           float mcoef, int last)
{
    extern __shared__ char smem[];
    float* sA = (float*)smem;              // 256 rows x 32 ci, SW128 rows (32 KB)
    float* sB = (float*)(smem + 32768);    // [tap][nbl 8][kblk 4][lane][2]  (72 KB)

    const int tid  = threadIdx.x;
    const int lane = tid & 31;
    const int w    = tid >> 5;
    const int wm   = w & 3;                // m32 chunk of 4
    const int wn   = w >> 2;               // n32 chunk of 2
    const int g    = lane >> 2;
    const int t    = lane & 3;

    const int n   = blockIdx.z;
    const int h0  = blockIdx.y * 2;
    const int co0 = blockIdx.x * 64;
    const int cb0 = co0 >> 3;              // global co_blk base
    constexpr int KH  = CIN / 32;
    constexpr int NBG = COUT / 8;

    float acc[2][4][4];
#pragma unroll
    for (int c = 0; c < 2; c++)
#pragma unroll
        for (int nb = 0; nb < 4; nb++)
#pragma unroll
            for (int j = 0; j < 4; j++) acc[c][nb][j] = 0.f;

    for (int kh = 0; kh < KH; kh++) {
        if (kh) __syncthreads();
        // ---- stage A: 4 halo rows x 64 cols x 32 ci (tf32-rounded)
        for (int i4 = tid; i4 < 2048; i4 += 256) {
            int row = i4 >> 3;             // m' = rr*64 + cc
            int c4  = i4 & 7;
            int rr = row >> 6, cc = row & 63;
            int gh = h0 + rr - 1, gc = cc - 1;
            float4 v = make_float4(0.f, 0.f, 0.f, 0.f);
            if ((unsigned)gh < (unsigned)HH && (unsigned)gc < (unsigned)WW) {
                float4 s = *(const float4*)(in +
                    (size_t)((n * HH + gh) * WW + gc) * CIN + kh * 32 + c4 * 4);
                v.x = rna_tf32(s.x); v.y = rna_tf32(s.y);
                v.z = rna_tf32(s.z); v.w = rna_tf32(s.w);
            }
            *(float4*)((char*)sA + SWZ(row * 128 + c4 * 16)) = v;
        }
        // ---- stage B: fragment-ordered weight slice for this stage / co window
        for (int i4 = tid; i4 < 4608; i4 += 256) {
            int tap = i4 >> 9;
            int rem = i4 & 511;
            int nbl = rem >> 6;
            int q4  = rem & 63;
            float4 v = *(const float4*)(wgt +
                (size_t)(((kh * 9 + tap) * NBG + cb0 + nbl) * 256 + q4 * 4));
            *(float4*)(sB + (tap * 8 + nbl) * 256 + q4 * 4) = v;
        }
        __syncthreads();

        // ---- compute: 9 taps x 4 k8 blocks
#pragma unroll
        for (int tap = 0; tap < 9; tap++) {
            const int tapoff = (tap / 3) * 64 + (tap % 3);
#pragma unroll
            for (int kblk = 0; kblk < 4; kblk++) {
                const int k0 = kblk * 8;
                uint32_t a[2][4];
#pragma unroll
                for (int c = 0; c < 2; c++) {
                    int mb = wm * 32 + c * 16 + g + tapoff;   // fragment row m'
                    int x0 = (mb & 7) << 4;
                    int x1 = ((mb + 8) & 7) << 4;
                    const char* pA = (const char*)sA;
                    a[c][0] = *(const uint32_t*)(pA + mb * 128 +       (((k0 + t) * 4)     ^ x0));
                    a[c][1] = *(const uint32_t*)(pA + (mb + 8) * 128 + (((k0 + t) * 4)     ^ x1));
                    a[c][2] = *(const uint32_t*)(pA + mb * 128 +       (((k0 + t + 4) * 4) ^ x0));
                    a[c][3] = *(const uint32_t*)(pA + (mb + 8) * 128 + (((k0 + t + 4) * 4) ^ x1));
                }
#pragma unroll
                for (int nb = 0; nb < 4; nb++) {
                    float2 bv = *(const float2*)(sB +
                        ((tap * 8 + wn * 4 + nb) * 4 + kblk) * 64 + lane * 2);
                    uint32_t b[2];
                    b[0] = __float_as_uint(bv.x);
                    b[1] = __float_as_uint(bv.y);
                    mma_tf32(acc[0][nb], a[0], b);
                    mma_tf32(acc[1][nb], a[1], b);
                }
            }
        }
    }

    // ---- epilogue: fused FISTA ops on register fragments
#pragma unroll
    for (int c = 0; c < 2; c++) {
#pragma unroll
        for (int half = 0; half < 2; half++) {
            int m = wm * 32 + c * 16 + g + half * 8;   // pixel index in tile
            int rr = m >> 6, cc = m & 63;
            if (cc >= WW) continue;
            int h = h0 + rr;
            size_t pxb = (size_t)((n * HH + h) * WW + cc) * COUT + co0;
#pragma unroll
            for (int nb = 0; nb < 4; nb++) {
                int col = wn * 32 + nb * 8 + 2 * t;
                size_t o = pxb + col;
                float v0 = acc[c][nb][half * 2 + 0];
                float v1 = acc[c][nb][half * 2 + 1];
                if (MODE == 0) {
                    float2 r2;
                    r2.x = fmaxf(MU_C * v0 - THR_C, 0.f);
                    r2.y = fmaxf(MU_C * v1 - THR_C, 0.f);
                    *(float2*)(out0 + o) = r2;
                    *(float2*)(out1 + o) = r2;
                } else if (MODE == 1) {
                    float2 yv = *(const float2*)(aux0 + o);
                    float cn0 = fmaxf(yv.x + MU_C * v0 - THR_C, 0.f);
                    float cn1 = fmaxf(yv.y + MU_C * v1 - THR_C, 0.f);
                    if (last) {
                        out1[((size_t)(n * C2 + co0 + col) * HH + h) * WW + cc] = cn0;
                        out1[((size_t)(n * C2 + co0 + col + 1) * HH + h) * WW + cc] = cn1;
                    } else {
                        float2 cpv = *(const float2*)(aux1 + o);
                        float2 c2; c2.x = cn0; c2.y = cn1;
                        *(float2*)(out1 + o) = c2;
                        float2 y2;
                        y2.x = cn0 + mcoef * (cn0 - cpv.x);
                        y2.y = cn1 + mcoef * (cn1 - cpv.y);
                        *(float2*)(out0 + o) = y2;
                    }
                } else {
                    float2 xv = *(const float2*)(aux0 + o);
                    float2 r2;
                    r2.x = xv.x - v0;
                    r2.y = xv.y - v1;
                    *(float2*)(out0 + o) = r2;
                }
            }
        }
    }
}

// ---------------- launcher ----------------
extern "C" void kernel_launch(void* const* d_in, const int* in_sizes, int n_in,
                              void* d_out, int out_size)
{
    const float* x = (const float*)d_in[0];   // [16,64,56,56] NCHW
    const float* W = (const float*)d_in[1];   // [128,64,3,3]
    float* out = (float*)d_out;               // [16,128,56,56] NCHW

    float *Wf, *Wt, *xn, *y, *cp, *r;
    cudaGetSymbolAddress((void**)&Wf, g_Wf);
    cudaGetSymbolAddress((void**)&Wt, g_Wt);
    cudaGetSymbolAddress((void**)&xn, g_xn);
    cudaGetSymbolAddress((void**)&y,  g_y);
    cudaGetSymbolAddress((void**)&cp, g_cp);
    cudaGetSymbolAddress((void**)&r,  g_r);

    float mv[5];
    {
        double t = 1.0;
        for (int i = 0; i < 5; i++) {
            double tn = (1.0 + sqrt(1.0 + 4.0 * t * t)) / 2.0;
            mv[i] = (float)((t - 1.0) / tn);
            t = tn;
        }
    }

    const int SMEM = 32768 + 73728;   // 106496 B
    cudaFuncSetAttribute(mconv<C1, C2, 0>, cudaFuncAttributeMaxDynamicSharedMemorySize, SMEM);
    cudaFuncSetAttribute(mconv<C1, C2, 1>, cudaFuncAttributeMaxDynamicSharedMemorySize, SMEM);
    cudaFuncSetAttribute(mconv<C2, C1, 2>, cudaFuncAttributeMaxDynamicSharedMemorySize, SMEM);
    cudaFuncSetAttribute(mconv<C1, C2, 0>, cudaFuncAttributePreferredSharedMemoryCarveout, 100);
    cudaFuncSetAttribute(mconv<C1, C2, 1>, cudaFuncAttributePreferredSharedMemoryCarveout, 100);
    cudaFuncSetAttribute(mconv<C2, C1, 2>, cudaFuncAttributePreferredSharedMemoryCarveout, 100);

    int total = NB * HH * WW * C1;
    nchw2nhwc_kernel<<<(total + 255) / 256, 256>>>(x, xn);
    prep_w_kernel<<<128, 256>>>(W);

    dim3 blk(256, 1, 1);
    dim3 grid_f(C2 / 64, HH / 2, NB);   // (2, 28, 16)
    dim3 grid_t(C1 / 64, HH / 2, NB);   // (1, 28, 16)

    // iteration 0: c = shrink(MU * D^T x); y = c; cp = c
    mconv<C1, C2, 0><<<grid_f, blk, SMEM>>>(xn, Wf, nullptr, nullptr, y, cp, 0.f, 0);

    for (int it = 0; it < 5; it++) {
        // r = x - D y  (transpose conv + residual)
        mconv<C2, C1, 2><<<grid_t, blk, SMEM>>>(y, Wt, xn, nullptr, r, nullptr, 0.f, 0);
        // c_new = shrink(y + MU * D^T r); momentum
        const int last = (it == 4);
        mconv<C1, C2, 1><<<grid_f, blk, SMEM>>>(r, Wf, y, cp, y, last ? out : cp,
                                                mv[it], last);
    }
}